// round 6
// baseline (speedup 1.0000x reference)
#include <cuda_runtime.h>
#include <cstdint>

// ---------------------------------------------------------------------------
// Fused LSTM, persistent-cluster design for GB300 (sm_103a).
//
//   B=512, T=1024, D=64, U=128.  out = h_T  [512,128] fp32.
//
// 64 clusters x 2 CTAs (128 CTAs, 1/SM). Cluster = 8 batch rows. CTA rank r
// owns u-columns [64r,64r+64) of all 4 gates (256 output cols); the fused
// weight block [192 x 256] fp32 (rows 0..63 = W_*, rows 64..191 = U_*) is
// resident in SMEM. Per step: packed fma.rn.f32x2 GEMV (exact fp32), gate
// math with c in registers, h-half exchange via DSMEM st.shared::cluster,
// one cluster barrier per step (double-buffered [x;h] value buffer).
// ---------------------------------------------------------------------------

namespace {
constexpr int kB = 512;
constexpr int kT = 1024;
constexpr int kD = 64;
constexpr int kU = 128;
constexpr int kR = 8;              // batch rows per cluster
constexpr int kThreads = 128;
constexpr int kK = kD + kU;        // 192 fused K
constexpr int kKP = kK / 2;        // 96 k-pairs
constexpr int kCols = 256;         // per-CTA output columns (4 gates x 64 u)

constexpr int kWsmFloats  = kKP * kCols * 2;   // 49152 (192 KB)
constexpr int kVbufFloats = kK * kR;           // 1536 per buffer ([k][row])
constexpr int kGbufFloats = kR * kCols;        // 2048
constexpr int kVbufOff = kWsmFloats;
constexpr int kGbufOff = kWsmFloats + 2 * kVbufFloats;
constexpr int kSmemBytes = (kGbufOff + kGbufFloats) * 4;   // 217088 B
}  // namespace

typedef unsigned long long ull;

__device__ __forceinline__ ull pk2(float a, float b) {
    ull r;
    asm("mov.b64 %0, {%1, %2};" : "=l"(r) : "f"(a), "f"(b));
    return r;
}
__device__ __forceinline__ void upk2(ull v, float& a, float& b) {
    asm("mov.b64 {%0, %1}, %2;" : "=f"(a), "=f"(b) : "l"(v));
}
// packed dual fp32 FMA: d = a*b + d (exact fp32 on both lanes)
__device__ __forceinline__ void fma2(ull& d, ull a, ull b) {
    asm("fma.rn.f32x2 %0, %1, %2, %0;" : "+l"(d) : "l"(a), "l"(b));
}
__device__ __forceinline__ float sigf(float x) {
    return 1.0f / (1.0f + __expf(-x));
}
__device__ __forceinline__ float tanh_acc(float x) {
    float e = __expf(-2.0f * fabsf(x));
    float r = (1.0f - e) / (1.0f + e);
    return copysignf(r, x);
}
__device__ __forceinline__ uint32_t smem_u32(const void* p) {
    uint32_t a;
    asm("{ .reg .u64 t; cvta.to.shared.u64 t, %1; cvt.u32.u64 %0, t; }"
        : "=r"(a) : "l"(p));
    return a;
}

__global__ void __cluster_dims__(2, 1, 1) __launch_bounds__(kThreads, 1)
lstm_fused_kernel(const float* __restrict__ x,
                  const float* __restrict__ Wf, const float* __restrict__ Uf, const float* __restrict__ bf,
                  const float* __restrict__ Wi, const float* __restrict__ Ui, const float* __restrict__ bi,
                  const float* __restrict__ Wc, const float* __restrict__ Uc, const float* __restrict__ bc,
                  const float* __restrict__ Wo, const float* __restrict__ Uo, const float* __restrict__ bo,
                  float* __restrict__ out) {
    extern __shared__ float smem[];
    float* wsm   = smem;                       // [kp][j][parity] fp32
    float* vbuf0 = smem + kVbufOff;            // [k][row]: x rows k<64, h rows k>=64
    float* vbuf1 = vbuf0 + kVbufFloats;
    float* gbuf  = smem + kGbufOff;            // [row][256] gate pre-activations

    const int tid = threadIdx.x;
    uint32_t rank;
    asm("mov.u32 %0, %%cluster_ctarank;" : "=r"(rank));
    const int cl = blockIdx.x >> 1;            // cluster id -> batch row group

    // ---- one-time: stage fused weight block into SMEM -----------------------
    // wsm[kp*512 + j*2 + par] = M[2*kp+par][j],  j = gate*64 + u', u = rank*64+u'
    // Iterate (k, gate, u') with u' innermost so the 64-thread groups do
    // coalesced 256B global reads.
    for (int idx = tid; idx < kK * kCols; idx += kThreads) {
        int k   = idx >> 8;                    // 0..191
        int j   = idx & 255;                   // gate*64 + u'
        int g   = j >> 6;
        int u   = (int)rank * 64 + (j & 63);
        float w;
        if (k < kD) {
            const float* src = (g == 0) ? Wf : (g == 1) ? Wi : (g == 2) ? Wc : Wo;
            w = src[k * kU + u];
        } else {
            const float* src = (g == 0) ? Uf : (g == 1) ? Ui : (g == 2) ? Uc : Uo;
            w = src[(k - kD) * kU + u];
        }
        int kp  = k >> 1;
        int par = k & 1;
        wsm[kp * 512 + j * 2 + par] = w;
    }

    // ---- per-thread column / bias setup ------------------------------------
    const int j0 = 2 * tid;                    // thread owns cols j0, j0+1
    const int g0 = j0 >> 6;                    // same gate for both (j0 even)
    const int u0 = (int)rank * 64 + (j0 & 63);
    const float* bsrc = (g0 == 0) ? bf : (g0 == 1) ? bi : (g0 == 2) ? bc : bo;
    const ull bias0p = pk2(bsrc[u0], bsrc[u0]);
    const ull bias1p = pk2(bsrc[u0 + 1], bsrc[u0 + 1]);

    // x prefetch mapping: thread -> (row, 4-float d-group)
    const int xrow = tid & 7;
    const int xdg  = tid >> 3;                 // 0..15
    const float4* xbase =
        (const float4*)(x + ((size_t)(cl * kR + xrow) * kT) * kD) + xdg;

    // gate-math mapping: thread -> (u', rows 4*hi .. 4*hi+3)
    const int hi = tid >> 6;
    const int up = tid & 63;
    const int ug = (int)rank * 64 + up;

    // peer CTA's vbuf0 shared-address (cluster DSMEM)
    const uint32_t my_vb0 = smem_u32(vbuf0);
    uint32_t peer_vb0;
    {
        uint32_t prank = rank ^ 1u;
        asm("mapa.shared::cluster.u32 %0, %1, %2;"
            : "=r"(peer_vb0) : "r"(my_vb0), "r"(prank));
    }

    // ---- init state: h=0, c=0, load x_0 ------------------------------------
    {
        float4 x0 = __ldg(xbase);
        vbuf0[(xdg * 4 + 0) * kR + xrow] = x0.x;
        vbuf0[(xdg * 4 + 1) * kR + xrow] = x0.y;
        vbuf0[(xdg * 4 + 2) * kR + xrow] = x0.z;
        vbuf0[(xdg * 4 + 3) * kR + xrow] = x0.w;
        for (int i = tid; i < (kK - kD) * kR; i += kThreads)
            vbuf0[kD * kR + i] = 0.0f;
    }
    float creg[4] = {0.0f, 0.0f, 0.0f, 0.0f};
    __syncthreads();

    const float4* wq = (const float4*)wsm;     // [kp*128 + tid]

    int cur = 0;
    for (int t = 0; t < kT; ++t) {
        // prefetch x_{t+1} early (DRAM latency hidden behind the GEMV)
        float4 xn = make_float4(0.f, 0.f, 0.f, 0.f);
        if (t + 1 < kT) xn = __ldg(xbase + (size_t)(t + 1) * (kD / 4));

        const float* vb = cur ? vbuf1 : vbuf0;
        float*      vbn = cur ? vbuf0 : vbuf1;
        const ulonglong2* vq = (const ulonglong2*)vb;   // 4 f32x2 row-pairs / k

        // ---- fused GEMV: g = [x_t ; h] @ Wblk + bias -----------------------
        ull a00 = bias0p, a01 = bias0p, a02 = bias0p, a03 = bias0p;
        ull a10 = bias1p, a11 = bias1p, a12 = bias1p, a13 = bias1p;

#pragma unroll 4
        for (int kp = 0; kp < kKP; ++kp) {
            float4 w = wq[kp * 128 + tid];     // (j0,ke)(j0,ko)(j1,ke)(j1,ko)
            ulonglong2 v0 = vq[kp * 4 + 0];    // k even, rows 0..3
            ulonglong2 v1 = vq[kp * 4 + 1];    // k even, rows 4..7
            ulonglong2 v2 = vq[kp * 4 + 2];    // k odd,  rows 0..3
            ulonglong2 v3 = vq[kp * 4 + 3];    // k odd,  rows 4..7
            ull w00 = pk2(w.x, w.x);
            ull w01 = pk2(w.z, w.z);
            ull w10 = pk2(w.y, w.y);
            ull w11 = pk2(w.w, w.w);
            fma2(a00, v0.x, w00); fma2(a01, v0.y, w00);
            fma2(a02, v1.x, w00); fma2(a03, v1.y, w00);
            fma2(a10, v0.x, w01); fma2(a11, v0.y, w01);
            fma2(a12, v1.x, w01); fma2(a13, v1.y, w01);
            fma2(a00, v2.x, w10); fma2(a01, v2.y, w10);
            fma2(a02, v3.x, w10); fma2(a03, v3.y, w10);
            fma2(a10, v2.x, w11); fma2(a11, v2.y, w11);
            fma2(a12, v3.x, w11); fma2(a13, v3.y, w11);
        }

        // scatter gate pre-activations to gbuf[row][j]
        {
            ull ac0[4] = {a00, a01, a02, a03};
            ull ac1[4] = {a10, a11, a12, a13};
#pragma unroll
            for (int rp = 0; rp < 4; ++rp) {
                float c0lo, c0hi, c1lo, c1hi;
                upk2(ac0[rp], c0lo, c0hi);     // rows 2rp, 2rp+1 of col j0
                upk2(ac1[rp], c1lo, c1hi);     // rows 2rp, 2rp+1 of col j0+1
                *(float2*)&gbuf[(2 * rp + 0) * kCols + j0] = make_float2(c0lo, c1lo);
                *(float2*)&gbuf[(2 * rp + 1) * kCols + j0] = make_float2(c0hi, c1hi);
            }
        }
        __syncthreads();

        // ---- gate math + h exchange ----------------------------------------
        const uint32_t peer_vbn = peer_vb0 + (cur ? 0u : (uint32_t)(kVbufFloats * 4));
#pragma unroll
        for (int rr = 0; rr < 4; ++rr) {
            int row = hi * 4 + rr;
            const float* gr = gbuf + row * kCols + up;
            float f  = sigf(gr[0]);
            float ii = sigf(gr[64]);
            float cd = tanh_acc(gr[128]);
            float o  = sigf(gr[192]);
            float c  = f * creg[rr] + ii * cd;
            creg[rr] = c;
            float h  = o * tanh_acc(c);
            int off = (kD + ug) * kR + row;
            vbn[off] = h;                                         // own half
            asm volatile("st.shared::cluster.b32 [%0], %1;"       // peer half
                         :: "r"(peer_vbn + (uint32_t)(off * 4)),
                            "r"(__float_as_uint(h)) : "memory");
        }

        // stash prefetched x_{t+1}
        vbn[(xdg * 4 + 0) * kR + xrow] = xn.x;
        vbn[(xdg * 4 + 1) * kR + xrow] = xn.y;
        vbn[(xdg * 4 + 2) * kR + xrow] = xn.z;
        vbn[(xdg * 4 + 3) * kR + xrow] = xn.w;

        // release DSMEM h-writes + flip double buffer (one sync per step;
        // arrive has release, wait has acquire semantics -> peer stores visible)
        asm volatile("barrier.cluster.arrive.aligned;" ::: "memory");
        asm volatile("barrier.cluster.wait.aligned;"   ::: "memory");
        cur ^= 1;
    }

    // ---- emit h_T -----------------------------------------------------------
    const float* vb = cur ? vbuf1 : vbuf0;
#pragma unroll
    for (int rr = 0; rr < 4; ++rr) {
        int row = hi * 4 + rr;
        out[(size_t)(cl * kR + row) * kU + ug] = vb[(kD + ug) * kR + row];
    }
}

extern "C" void kernel_launch(void* const* d_in, const int* in_sizes, int n_in,
                              void* d_out, int out_size) {
    (void)in_sizes; (void)n_in; (void)out_size;
    const float* x  = (const float*)d_in[0];
    const float* Wf = (const float*)d_in[1];
    const float* Uf = (const float*)d_in[2];
    const float* bf = (const float*)d_in[3];
    const float* Wi = (const float*)d_in[4];
    const float* Ui = (const float*)d_in[5];
    const float* bi = (const float*)d_in[6];
    const float* Wc = (const float*)d_in[7];
    const float* Uc = (const float*)d_in[8];
    const float* bc = (const float*)d_in[9];
    const float* Wo = (const float*)d_in[10];
    const float* Uo = (const float*)d_in[11];
    const float* bo = (const float*)d_in[12];
    float* out = (float*)d_out;

    cudaFuncSetAttribute(lstm_fused_kernel,
                         cudaFuncAttributeMaxDynamicSharedMemorySize, kSmemBytes);
    const int grid = (kB / kR) * 2;   // 64 clusters x 2 CTAs = 128
    lstm_fused_kernel<<<grid, kThreads, kSmemBytes>>>(
        x, Wf, Uf, bf, Wi, Ui, bi, Wc, Uc, bc, Wo, Uo, bo, out);
}

// round 7
// speedup vs baseline: 1.1866x; 1.1866x over previous
#include <cuda_runtime.h>
#include <cstdint>

// ---------------------------------------------------------------------------
// Fused LSTM, persistent-cluster design for GB300 (sm_103a).   Round 7.
//
//   B=512, T=1024, D=64, U=128.  out = h_T  [512,128] fp32.
//
// 64 clusters x 2 CTAs (128 CTAs, 1/SM), 256 threads/CTA (2 warps/SMSP).
// CTA rank r owns u-columns [64r,64r+64) of all 4 gates (256 output cols);
// fused weight block [192 x 256] fp32 resident in SMEM.
// GEMV is K-SPLIT: warps 0-3 accumulate kp 0..47, warps 4-7 kp 48..95;
// halves combine through an 8KB partial buffer. This doubles warps/SMSP
// (latency hiding) without increasing smem value-broadcast traffic.
// Gate math (c in registers, 2 rows/thread), h-half exchange via DSMEM
// st.shared::cluster, one cluster barrier per step, double-buffered values.
// ---------------------------------------------------------------------------

namespace {
constexpr int kB = 512;
constexpr int kT = 1024;
constexpr int kD = 64;
constexpr int kU = 128;
constexpr int kR = 8;               // batch rows per cluster
constexpr int kThreads = 256;
constexpr int kK = kD + kU;         // 192 fused K
constexpr int kKP = kK / 2;         // 96 k-pairs
constexpr int kKPH = kKP / 2;       // 48 k-pairs per half
constexpr int kCols = 256;          // per-CTA output columns

constexpr int kWsmFloats  = kKP * kCols * 2;    // 49152 (192 KB)
constexpr int kVbufFloats = kK * kR;            // 1536 per buffer ([k][row])
constexpr int kGbufFloats = kR * kCols;         // 2048
constexpr int kPbufFloats = 128 * 16;           // 2048 partial sums
constexpr int kVbufOff = kWsmFloats;
constexpr int kGbufOff = kVbufOff + 2 * kVbufFloats;
constexpr int kPbufOff = kGbufOff + kGbufFloats;
constexpr int kSmemBytes = (kPbufOff + kPbufFloats) * 4;   // 225280 B
}  // namespace

typedef unsigned long long ull;

__device__ __forceinline__ ull pk2(float a, float b) {
    ull r;
    asm("mov.b64 %0, {%1, %2};" : "=l"(r) : "f"(a), "f"(b));
    return r;
}
__device__ __forceinline__ void upk2(ull v, float& a, float& b) {
    asm("mov.b64 {%0, %1}, %2;" : "=f"(a), "=f"(b) : "l"(v));
}
// packed dual fp32 FMA / ADD (exact fp32 on both lanes)
__device__ __forceinline__ void fma2(ull& d, ull a, ull b) {
    asm("fma.rn.f32x2 %0, %1, %2, %0;" : "+l"(d) : "l"(a), "l"(b));
}
__device__ __forceinline__ void add2(ull& d, ull a) {
    asm("add.rn.f32x2 %0, %0, %1;" : "+l"(d) : "l"(a));
}
__device__ __forceinline__ float sigf(float x) {
    return 1.0f / (1.0f + __expf(-x));
}
__device__ __forceinline__ float tanh_acc(float x) {
    float e = __expf(-2.0f * fabsf(x));
    float r = (1.0f - e) / (1.0f + e);
    return copysignf(r, x);
}
__device__ __forceinline__ uint32_t smem_u32(const void* p) {
    uint32_t a;
    asm("{ .reg .u64 t; cvta.to.shared.u64 t, %1; cvt.u32.u64 %0, t; }"
        : "=r"(a) : "l"(p));
    return a;
}

__global__ void __cluster_dims__(2, 1, 1) __launch_bounds__(kThreads, 1)
lstm_fused_kernel(const float* __restrict__ x,
                  const float* __restrict__ Wf, const float* __restrict__ Uf, const float* __restrict__ bf,
                  const float* __restrict__ Wi, const float* __restrict__ Ui, const float* __restrict__ bi,
                  const float* __restrict__ Wc, const float* __restrict__ Uc, const float* __restrict__ bc,
                  const float* __restrict__ Wo, const float* __restrict__ Uo, const float* __restrict__ bo,
                  float* __restrict__ out) {
    extern __shared__ float smem[];
    float* wsm   = smem;                       // [kp][j][parity] fp32
    float* vbuf0 = smem + kVbufOff;            // [k][row]: x rows k<64, h rows k>=64
    float* vbuf1 = vbuf0 + kVbufFloats;
    float* gbuf  = smem + kGbufOff;            // [row][256] gate pre-activations
    ull*   pbuf  = (ull*)(smem + kPbufOff);    // [slot 0..7][tidw] partial f32x2

    const int tid = threadIdx.x;
    uint32_t rank;
    asm("mov.u32 %0, %%cluster_ctarank;" : "=r"(rank));
    const int cl = blockIdx.x >> 1;            // cluster id -> batch row group

    const int half = tid >> 7;                 // 0: kp 0..47, 1: kp 48..95
    const int tidw = tid & 127;                // column-thread id within half

    // ---- one-time: stage fused weight block into SMEM -----------------------
    // wsm[kp*512 + j*2 + par] = M[2*kp+par][j], j = gate*64+u', u = rank*64+u'
    for (int idx = tid; idx < kK * kCols; idx += kThreads) {
        int k   = idx >> 8;                    // 0..191
        int j   = idx & 255;
        int g   = j >> 6;
        int u   = (int)rank * 64 + (j & 63);
        float w;
        if (k < kD) {
            const float* src = (g == 0) ? Wf : (g == 1) ? Wi : (g == 2) ? Wc : Wo;
            w = src[k * kU + u];
        } else {
            const float* src = (g == 0) ? Uf : (g == 1) ? Ui : (g == 2) ? Uc : Uo;
            w = src[(k - kD) * kU + u];
        }
        wsm[(k >> 1) * 512 + j * 2 + (k & 1)] = w;
    }

    // ---- per-thread column / bias setup (both halves share column mapping) --
    const int j0 = 2 * tidw;                   // this thread's cols j0, j0+1
    const int g0 = j0 >> 6;
    const int u0 = (int)rank * 64 + (j0 & 63);
    const float* bsrc = (g0 == 0) ? bf : (g0 == 1) ? bi : (g0 == 2) ? bc : bo;
    // bias applied only in the low half's accumulators
    const ull bias0p = half ? 0ull : pk2(bsrc[u0], bsrc[u0]);
    const ull bias1p = half ? 0ull : pk2(bsrc[u0 + 1], bsrc[u0 + 1]);

    // x prefetch/stash mapping (HIGH half only): thread -> (row, 4-float dgrp)
    const int xrow = tidw & 7;
    const int xdg  = tidw >> 3;                // 0..15
    const float4* xbase =
        (const float4*)(x + ((size_t)(cl * kR + xrow) * kT) * kD) + xdg;

    // gate-math mapping: 256 threads -> (u', 2 rows each)
    const int r0 = (tid >> 6) * 2;             // rows r0, r0+1
    const int up = tid & 63;
    const int ug = (int)rank * 64 + up;

    // peer CTA's vbuf0 shared-address (cluster DSMEM)
    const uint32_t my_vb0 = smem_u32(vbuf0);
    uint32_t peer_vb0;
    {
        uint32_t prank = rank ^ 1u;
        asm("mapa.shared::cluster.u32 %0, %1, %2;"
            : "=r"(peer_vb0) : "r"(my_vb0), "r"(prank));
    }

    // ---- init state: h=0, c=0, load x_0 ------------------------------------
    if (half) {
        float4 x0 = __ldg(xbase);
        vbuf0[(xdg * 4 + 0) * kR + xrow] = x0.x;
        vbuf0[(xdg * 4 + 1) * kR + xrow] = x0.y;
        vbuf0[(xdg * 4 + 2) * kR + xrow] = x0.z;
        vbuf0[(xdg * 4 + 3) * kR + xrow] = x0.w;
    }
    for (int i = tid; i < (kK - kD) * kR; i += kThreads)
        vbuf0[kD * kR + i] = 0.0f;
    float creg[2] = {0.0f, 0.0f};
    __syncthreads();

    const float4* wq = (const float4*)wsm;     // [kp*128 + tidw]
    const int kp0 = half * kKPH;

    int cur = 0;
    for (int t = 0; t < kT; ++t) {
        // prefetch x_{t+1} early (DRAM latency hidden behind the GEMV)
        float4 xn = make_float4(0.f, 0.f, 0.f, 0.f);
        if (half && (t + 1 < kT)) xn = __ldg(xbase + (size_t)(t + 1) * (kD / 4));

        const float* vb = cur ? vbuf1 : vbuf0;
        float*      vbn = cur ? vbuf0 : vbuf1;
        const ulonglong2* vq = (const ulonglong2*)vb;   // 4 f32x2 row-pairs / k

        // ---- K-split GEMV: partial g = [x_t ; h](kp-half) @ Wblk ----------
        ull a00 = bias0p, a01 = bias0p, a02 = bias0p, a03 = bias0p;
        ull a10 = bias1p, a11 = bias1p, a12 = bias1p, a13 = bias1p;

#pragma unroll 4
        for (int kp = kp0; kp < kp0 + kKPH; ++kp) {
            float4 w = wq[kp * 128 + tidw];    // (j0,ke)(j0,ko)(j1,ke)(j1,ko)
            ulonglong2 v0 = vq[kp * 4 + 0];    // k even, rows 0..3
            ulonglong2 v1 = vq[kp * 4 + 1];    // k even, rows 4..7
            ulonglong2 v2 = vq[kp * 4 + 2];    // k odd,  rows 0..3
            ulonglong2 v3 = vq[kp * 4 + 3];    // k odd,  rows 4..7
            ull w00 = pk2(w.x, w.x);
            ull w01 = pk2(w.z, w.z);
            ull w10 = pk2(w.y, w.y);
            ull w11 = pk2(w.w, w.w);
            fma2(a00, v0.x, w00); fma2(a01, v0.y, w00);
            fma2(a02, v1.x, w00); fma2(a03, v1.y, w00);
            fma2(a10, v0.x, w01); fma2(a11, v0.y, w01);
            fma2(a12, v1.x, w01); fma2(a13, v1.y, w01);
            fma2(a00, v2.x, w10); fma2(a01, v2.y, w10);
            fma2(a02, v3.x, w10); fma2(a03, v3.y, w10);
            fma2(a10, v2.x, w11); fma2(a11, v2.y, w11);
            fma2(a12, v3.x, w11); fma2(a13, v3.y, w11);
        }

        if (half) {
            // high half: publish partials, then stash x_{t+1} into vbn
            pbuf[0 * 128 + tidw] = a00;
            pbuf[1 * 128 + tidw] = a01;
            pbuf[2 * 128 + tidw] = a02;
            pbuf[3 * 128 + tidw] = a03;
            pbuf[4 * 128 + tidw] = a10;
            pbuf[5 * 128 + tidw] = a11;
            pbuf[6 * 128 + tidw] = a12;
            pbuf[7 * 128 + tidw] = a13;
            vbn[(xdg * 4 + 0) * kR + xrow] = xn.x;
            vbn[(xdg * 4 + 1) * kR + xrow] = xn.y;
            vbn[(xdg * 4 + 2) * kR + xrow] = xn.z;
            vbn[(xdg * 4 + 3) * kR + xrow] = xn.w;
        }
        __syncthreads();

        if (!half) {
            // low half: combine and scatter gate pre-activations to gbuf
            add2(a00, pbuf[0 * 128 + tidw]);
            add2(a01, pbuf[1 * 128 + tidw]);
            add2(a02, pbuf[2 * 128 + tidw]);
            add2(a03, pbuf[3 * 128 + tidw]);
            add2(a10, pbuf[4 * 128 + tidw]);
            add2(a11, pbuf[5 * 128 + tidw]);
            add2(a12, pbuf[6 * 128 + tidw]);
            add2(a13, pbuf[7 * 128 + tidw]);
            ull ac0[4] = {a00, a01, a02, a03};
            ull ac1[4] = {a10, a11, a12, a13};
#pragma unroll
            for (int rp = 0; rp < 4; ++rp) {
                float c0lo, c0hi, c1lo, c1hi;
                upk2(ac0[rp], c0lo, c0hi);     // rows 2rp, 2rp+1 of col j0
                upk2(ac1[rp], c1lo, c1hi);     // rows 2rp, 2rp+1 of col j0+1
                *(float2*)&gbuf[(2 * rp + 0) * kCols + j0] = make_float2(c0lo, c1lo);
                *(float2*)&gbuf[(2 * rp + 1) * kCols + j0] = make_float2(c0hi, c1hi);
            }
        }
        __syncthreads();

        // ---- gate math (2 rows per thread) + h exchange --------------------
        const uint32_t peer_vbn = peer_vb0 + (cur ? 0u : (uint32_t)(kVbufFloats * 4));
#pragma unroll
        for (int rr = 0; rr < 2; ++rr) {
            int row = r0 + rr;
            const float* gr = gbuf + row * kCols + up;
            float f  = sigf(gr[0]);
            float ii = sigf(gr[64]);
            float cd = tanh_acc(gr[128]);
            float o  = sigf(gr[192]);
            float c  = f * creg[rr] + ii * cd;
            creg[rr] = c;
            float h  = o * tanh_acc(c);
            int off = (kD + ug) * kR + row;
            vbn[off] = h;                                         // own half
            asm volatile("st.shared::cluster.b32 [%0], %1;"       // peer half
                         :: "r"(peer_vbn + (uint32_t)(off * 4)),
                            "r"(__float_as_uint(h)) : "memory");
        }

        // release DSMEM h-writes + flip double buffer (one cluster sync/step)
        asm volatile("barrier.cluster.arrive.aligned;" ::: "memory");
        asm volatile("barrier.cluster.wait.aligned;"   ::: "memory");
        cur ^= 1;
    }

    // ---- emit h_T (own u-half was written locally) --------------------------
    const float* vb = cur ? vbuf1 : vbuf0;
#pragma unroll
    for (int rr = 0; rr < 2; ++rr) {
        int row = r0 + rr;
        out[(size_t)(cl * kR + row) * kU + ug] = vb[(kD + ug) * kR + row];
    }
}

extern "C" void kernel_launch(void* const* d_in, const int* in_sizes, int n_in,
                              void* d_out, int out_size) {
    (void)in_sizes; (void)n_in; (void)out_size;
    const float* x  = (const float*)d_in[0];
    const float* Wf = (const float*)d_in[1];
    const float* Uf = (const float*)d_in[2];
    const float* bf = (const float*)d_in[3];
    const float* Wi = (const float*)d_in[4];
    const float* Ui = (const float*)d_in[5];
    const float* bi = (const float*)d_in[6];
    const float* Wc = (const float*)d_in[7];
    const float* Uc = (const float*)d_in[8];
    const float* bc = (const float*)d_in[9];
    const float* Wo = (const float*)d_in[10];
    const float* Uo = (const float*)d_in[11];
    const float* bo = (const float*)d_in[12];
    float* out = (float*)d_out;

    cudaFuncSetAttribute(lstm_fused_kernel,
                         cudaFuncAttributeMaxDynamicSharedMemorySize, kSmemBytes);
    const int grid = (kB / kR) * 2;   // 64 clusters x 2 CTAs = 128
    lstm_fused_kernel<<<grid, kThreads, kSmemBytes>>>(
        x, Wf, Uf, bf, Wi, Ui, bi, Wc, Uc, bc, Wo, Uo, bo, out);
}

// round 8
// speedup vs baseline: 1.2871x; 1.0847x over previous
#include <cuda_runtime.h>
#include <cstdint>

// ---------------------------------------------------------------------------
// Fused LSTM, persistent-cluster design for GB300 (sm_103a).   Round 8.
//
//   B=512, T=1024, D=64, U=128.  out = h_T  [512,128] fp32.
//
// 64 clusters x 2 CTAs (128 CTAs, 1/SM), 512 threads/CTA (4 warps/SMSP).
// CTA rank r owns u-columns [64r,64r+64) of all 4 gates (256 output cols);
// fused weight block [192 x 256] fp32 resident in SMEM, layout [kp][j][par].
// Values stored [kp][row][par] so LDS.128 yields (k-even,k-odd) f32x2 pairs,
// matching the weight float4's (ke,ko) pairs -> fma.rn.f32x2 with ZERO
// packing movs; accumulator lanes carry the two k-parity partial sums,
// lane-summed once per step in the epilogue.
// GEMV is 4-way K-SPLIT (24 kp per quarter); quarters 1-3 publish partials
// to pbuf, quarter 0 combines (+bias) and scatters to gbuf (aliased over
// pbuf, guarded by an extra syncthreads). Gate math: 512 threads, 1 (row,u)
// each, c in a register. h exchanged to the peer CTA via st.shared::cluster,
// one cluster barrier per step. x is single-buffered (stashed after sync1);
// h is double-buffered (peer may run ahead within a step).
// ---------------------------------------------------------------------------

namespace {
constexpr int kB = 512;
constexpr int kT = 1024;
constexpr int kD = 64;
constexpr int kU = 128;
constexpr int kR = 8;                // batch rows per cluster
constexpr int kThreads = 512;
constexpr int kKPX = kD / 2;         // 32 x k-pairs
constexpr int kHKP = kU / 2;         // 64 h k-pairs
constexpr int kKP  = kKPX + kHKP;    // 96 total k-pairs
constexpr int kCols = 256;           // per-CTA output columns

constexpr int kWsmFloats = kKP * kCols * 2;       // 49152 (192 KB)
constexpr int kVxOff   = kWsmFloats;              // x values: [xkp][row][par] = 512 f
constexpr int kHbOff   = kVxOff + kKPX * 16;      // two h buffers, 1024 f each
constexpr int kPbufOff = kHbOff + 2 * kHKP * 16;  // partials float2[3][8][128]
constexpr int kPbufFloats = 3 * kR * 128 * 2;     // 6144 floats (24 KB)
constexpr int kSmemBytes  = (kPbufOff + kPbufFloats) * 4;   // 231424 B
}  // namespace

typedef unsigned long long ull;

__device__ __forceinline__ ull pk2(float a, float b) {
    ull r;
    asm("mov.b64 %0, {%1, %2};" : "=l"(r) : "f"(a), "f"(b));
    return r;
}
__device__ __forceinline__ void upk2(ull v, float& a, float& b) {
    asm("mov.b64 {%0, %1}, %2;" : "=f"(a), "=f"(b) : "l"(v));
}
// packed dual fp32 FMA / ADD (exact fp32 on both lanes)
__device__ __forceinline__ void fma2(ull& d, ull a, ull b) {
    asm("fma.rn.f32x2 %0, %1, %2, %0;" : "+l"(d) : "l"(a), "l"(b));
}
__device__ __forceinline__ void add2(ull& d, ull a) {
    asm("add.rn.f32x2 %0, %0, %1;" : "+l"(d) : "l"(a));
}
__device__ __forceinline__ float rcpa(float x) {
    float r;
    asm("rcp.approx.f32 %0, %1;" : "=f"(r) : "f"(x));
    return r;
}
__device__ __forceinline__ float sigf(float x) {
    return rcpa(1.0f + __expf(-x));            // MUFU ex2 + MUFU rcp
}
__device__ __forceinline__ float tanh_acc(float x) {
    float e = __expf(-2.0f * fabsf(x));
    float r = (1.0f - e) * rcpa(1.0f + e);
    return copysignf(r, x);
}
__device__ __forceinline__ uint32_t smem_u32(const void* p) {
    uint32_t a;
    asm("{ .reg .u64 t; cvta.to.shared.u64 t, %1; cvt.u32.u64 %0, t; }"
        : "=r"(a) : "l"(p));
    return a;
}

// GEMV over k-pairs [kp0, kp1) of one value region.
//   w2: weight pairs, GLOBAL kp index = kp + wofs
//   v2: value pairs of this region, LOCAL kp index
__device__ __forceinline__ void gemv_part(const ulonglong2* __restrict__ w2,
                                          const ulonglong2* __restrict__ v2,
                                          int wofs, int kp0, int kp1, int tidw,
                                          ull a0[8], ull a1[8]) {
#pragma unroll 8
    for (int kp = kp0; kp < kp1; ++kp) {
        ulonglong2 w = w2[(kp + wofs) * 128 + tidw];  // .x=(ke,ko)@j0 .y=@j1
        ulonglong2 vA = v2[kp * 4 + 0];               // rows 0,1
        ulonglong2 vB = v2[kp * 4 + 1];               // rows 2,3
        ulonglong2 vC = v2[kp * 4 + 2];               // rows 4,5
        ulonglong2 vD = v2[kp * 4 + 3];               // rows 6,7
        fma2(a0[0], vA.x, w.x); fma2(a0[1], vA.y, w.x);
        fma2(a0[2], vB.x, w.x); fma2(a0[3], vB.y, w.x);
        fma2(a0[4], vC.x, w.x); fma2(a0[5], vC.y, w.x);
        fma2(a0[6], vD.x, w.x); fma2(a0[7], vD.y, w.x);
        fma2(a1[0], vA.x, w.y); fma2(a1[1], vA.y, w.y);
        fma2(a1[2], vB.x, w.y); fma2(a1[3], vB.y, w.y);
        fma2(a1[4], vC.x, w.y); fma2(a1[5], vC.y, w.y);
        fma2(a1[6], vD.x, w.y); fma2(a1[7], vD.y, w.y);
    }
}

__global__ void __cluster_dims__(2, 1, 1) __launch_bounds__(kThreads, 1)
lstm_fused_kernel(const float* __restrict__ x,
                  const float* __restrict__ Wf, const float* __restrict__ Uf, const float* __restrict__ bf,
                  const float* __restrict__ Wi, const float* __restrict__ Ui, const float* __restrict__ bi,
                  const float* __restrict__ Wc, const float* __restrict__ Uc, const float* __restrict__ bc,
                  const float* __restrict__ Wo, const float* __restrict__ Uo, const float* __restrict__ bo,
                  float* __restrict__ out) {
    extern __shared__ float smem[];
    float* wsm  = smem;                        // [kp][j][par]
    float* vx   = smem + kVxOff;               // [xkp][row][par]  (single buf)
    float* hb0  = smem + kHbOff;               // [hkp][row][par]  (double buf)
    float* hb1  = hb0 + kHKP * 16;
    float* pbufF = smem + kPbufOff;            // partials; gbuf aliases this
    ull*   pb2   = (ull*)pbufF;                // float2 slots [(qq*8+r)*128+tidw]

    const int tid = threadIdx.x;
    uint32_t rank;
    asm("mov.u32 %0, %%cluster_ctarank;" : "=r"(rank));
    const int cl = blockIdx.x >> 1;            // cluster id -> batch row group

    const int q    = tid >> 7;                 // K-quarter 0..3
    const int tidw = tid & 127;                // column-thread id in quarter

    // ---- one-time: stage fused weight block into SMEM -----------------------
    // wsm[(k>>1)*512 + j*2 + (k&1)] = M[k][j], j = gate*64+u', u = rank*64+u'
    for (int idx = tid; idx < 192 * kCols; idx += kThreads) {
        int k = idx >> 8;
        int j = idx & 255;
        int g = j >> 6;
        int u = (int)rank * 64 + (j & 63);
        float w;
        if (k < kD) {
            const float* src = (g == 0) ? Wf : (g == 1) ? Wi : (g == 2) ? Wc : Wo;
            w = src[k * kU + u];
        } else {
            const float* src = (g == 0) ? Uf : (g == 1) ? Ui : (g == 2) ? Uc : Uo;
            w = src[(k - kD) * kU + u];
        }
        wsm[(k >> 1) * 512 + j * 2 + (k & 1)] = w;
    }

    // ---- per-thread column / bias -------------------------------------------
    const int j0 = 2 * tidw;                   // cols j0, j0+1 (same gate)
    const int g0 = j0 >> 6;
    const int u0 = (int)rank * 64 + (j0 & 63);
    const float* bsrc = (g0 == 0) ? bf : (g0 == 1) ? bi : (g0 == 2) ? bc : bo;
    const ull biasp = pk2(bsrc[u0], bsrc[u0 + 1]);     // used by q0 only

    // x prefetch/stash mapping (quarter 3): thread -> (row, 4-float d-group)
    const int xrow = tidw & 7;
    const int xdg  = tidw >> 3;                // 0..15
    const float4* xbase =
        (const float4*)(x + ((size_t)(cl * kR + xrow) * kT) * kD) + xdg;

    // gate-math mapping: 512 threads -> 1 (row, u') each
    const int grow = tid >> 6;                 // 0..7
    const int gup  = tid & 63;
    const int gu   = (int)rank * 64 + gup;
    const int hoff = (gu >> 1) * 16 + grow * 2 + (gu & 1);  // into [hkp][row][par]

    // peer CTA's hb0 shared-address (cluster DSMEM)
    const uint32_t my_hb0 = smem_u32(hb0);
    uint32_t peer_hb0;
    {
        uint32_t prank = rank ^ 1u;
        asm("mapa.shared::cluster.u32 %0, %1, %2;"
            : "=r"(peer_hb0) : "r"(my_hb0), "r"(prank));
    }

    // ---- init: h0 = 0 (own buffer only!), x_0 staged ------------------------
    for (int i = tid; i < kHKP * 16; i += kThreads) hb0[i] = 0.0f;
    if (q == 3) {
        float4 x0 = __ldg(xbase);
        // d = xdg*4+dd -> vx[(d>>1)*16 + xrow*2 + (d&1)]
        *(float2*)&vx[(2 * xdg + 0) * 16 + xrow * 2] = make_float2(x0.x, x0.y);
        *(float2*)&vx[(2 * xdg + 1) * 16 + xrow * 2] = make_float2(x0.z, x0.w);
    }
    float creg = 0.0f;
    __syncthreads();

    const ulonglong2* w2  = (const ulonglong2*)wsm;
    const ulonglong2* vx2 = (const ulonglong2*)vx;

    // per-quarter GEMV ranges over global kp [q*24, q*24+24)
    const int xk0 = (q * 24 < kKPX) ? q * 24 : kKPX;
    const int xk1 = (q * 24 + 24 < kKPX) ? q * 24 + 24 : kKPX;
    const int hk0 = (q * 24 > kKPX) ? q * 24 - kKPX : 0;
    const int hk1 = q * 24 + 24 - kKPX;        // valid only when > hk0

    int cur = 0;
    for (int t = 0; t < kT; ++t) {
        // prefetch x_{t+1} (quarter 3 only; DRAM hidden behind GEMV)
        float4 xn = make_float4(0.f, 0.f, 0.f, 0.f);
        if (q == 3 && (t + 1 < kT)) xn = __ldg(xbase + (size_t)(t + 1) * (kD / 4));

        const ulonglong2* hq2 = (const ulonglong2*)(cur ? hb1 : hb0);
        float* hbn = cur ? hb0 : hb1;

        // ---- K-split GEMV (lanes = k-parity partials, no packing movs) -----
        ull a0[8], a1[8];
#pragma unroll
        for (int r = 0; r < 8; ++r) { a0[r] = 0ull; a1[r] = 0ull; }
        if (xk0 < xk1) gemv_part(w2, vx2, 0, xk0, xk1, tidw, a0, a1);
        if (hk1 > hk0) gemv_part(w2, hq2, kKPX, hk0, hk1, tidw, a0, a1);

        // lane-sum epilogue: gf[r] = (sum_j0, sum_j1) packed
        ull gfp[8];
#pragma unroll
        for (int r = 0; r < 8; ++r) {
            float s0lo, s0hi, s1lo, s1hi;
            upk2(a0[r], s0lo, s0hi);
            upk2(a1[r], s1lo, s1hi);
            gfp[r] = pk2(s0lo + s0hi, s1lo + s1hi);
        }

        if (q != 0) {
#pragma unroll
            for (int r = 0; r < 8; ++r)
                pb2[((q - 1) * 8 + r) * 128 + tidw] = gfp[r];
        }
        __syncthreads();                       // sync1: pbuf ready; x reads done

        if (q == 0) {
#pragma unroll
            for (int r = 0; r < 8; ++r) {
                add2(gfp[r], pb2[(0 * 8 + r) * 128 + tidw]);
                add2(gfp[r], pb2[(1 * 8 + r) * 128 + tidw]);
                add2(gfp[r], pb2[(2 * 8 + r) * 128 + tidw]);
                add2(gfp[r], biasp);
            }
        }
        if (q == 3) {                          // stash x_{t+1} (readers done)
            *(float2*)&vx[(2 * xdg + 0) * 16 + xrow * 2] = make_float2(xn.x, xn.y);
            *(float2*)&vx[(2 * xdg + 1) * 16 + xrow * 2] = make_float2(xn.z, xn.w);
        }
        __syncthreads();                       // sync2: pbuf reads done

        if (q == 0) {                          // scatter to gbuf (aliases pbuf)
#pragma unroll
            for (int r = 0; r < 8; ++r)
                *(ull*)&pbufF[r * kCols + j0] = gfp[r];
        }
        __syncthreads();                       // sync3: gbuf ready

        // ---- gate math: 1 (row,u') per thread ------------------------------
        {
            const float* gb = pbufF + grow * kCols + gup;
            float f  = sigf(gb[0]);
            float ii = sigf(gb[64]);
            float cd = tanh_acc(gb[128]);
            float o  = sigf(gb[192]);
            float c  = f * creg + ii * cd;
            creg = c;
            float h  = o * tanh_acc(c);
            hbn[hoff] = h;                                    // own u-half
            uint32_t paddr = peer_hb0 +
                (uint32_t)(((cur ? 0 : kHKP * 16) + hoff) * 4);
            asm volatile("st.shared::cluster.b32 [%0], %1;"   // peer's copy
                         :: "r"(paddr), "r"(__float_as_uint(h)) : "memory");
            if (t == kT - 1)
                out[(size_t)(cl * kR + grow) * kU + gu] = h;
        }

        // release DSMEM h-writes + lockstep the cluster (one barrier/step)
        asm volatile("barrier.cluster.arrive.aligned;" ::: "memory");
        asm volatile("barrier.cluster.wait.aligned;"   ::: "memory");
        cur ^= 1;
    }
}

extern "C" void kernel_launch(void* const* d_in, const int* in_sizes, int n_in,
                              void* d_out, int out_size) {
    (void)in_sizes; (void)n_in; (void)out_size;
    const float* x  = (const float*)d_in[0];
    const float* Wf = (const float*)d_in[1];
    const float* Uf = (const float*)d_in[2];
    const float* bf = (const float*)d_in[3];
    const float* Wi = (const float*)d_in[4];
    const float* Ui = (const float*)d_in[5];
    const float* bi = (const float*)d_in[6];
    const float* Wc = (const float*)d_in[7];
    const float* Uc = (const float*)d_in[8];
    const float* bc = (const float*)d_in[9];
    const float* Wo = (const float*)d_in[10];
    const float* Uo = (const float*)d_in[11];
    const float* bo = (const float*)d_in[12];
    float* out = (float*)d_out;

    cudaFuncSetAttribute(lstm_fused_kernel,
                         cudaFuncAttributeMaxDynamicSharedMemorySize, kSmemBytes);
    const int grid = (kB / kR) * 2;   // 64 clusters x 2 CTAs = 128
    lstm_fused_kernel<<<grid, kThreads, kSmemBytes>>>(
        x, Wf, Uf, bf, Wi, Ui, bi, Wc, Uc, bc, Wo, Uo, bo, out);
}

// round 11
// speedup vs baseline: 1.2979x; 1.0084x over previous
#include <cuda_runtime.h>
#include <cstdint>

// ---------------------------------------------------------------------------
// Fused LSTM, persistent-cluster design for GB300 (sm_103a).   Round 10.
//
//   B=512, T=1024, D=64, U=128.  out = h_T  [512,128] fp32.
//
// 64 clusters x 2 CTAs, 512 threads/CTA. CTA rank r owns u-cols [64r,64r+64)
// of all 4 gates; fused weight block [192x256] fp32 in SMEM.
// PIPELINED STEP (R9 overlap) on R8's PROVEN sync skeleton (no mbarriers):
//   h-part GEMV (64 kp, 4-way split, accumulating onto carried x(t) partials)
//   -> publish partials -> __syncthreads ->
//   { q0: combine+bias -> gbuf -> gate math -> h stores (own + peer DSMEM) }
//   OVERLAPPED WITH
//   { q1-3: x-part GEMV for step t+1 (32 kp, 3-way) + x prefetch/stash }
//   -> barrier.cluster (arrive+wait, all threads: rejoin + release h stores)
// h double-buffered; x single-buffered (stash after reads, bar.sync 2).
// gbuf aliases pbuf slot0 word-exactly (same ull ownership per thread).
// ---------------------------------------------------------------------------

namespace {
constexpr int kT = 1024;
constexpr int kD = 64;
constexpr int kU = 128;
constexpr int kR = 8;                 // batch rows per cluster
constexpr int kThreads = 512;
constexpr int kXKP = kD / 2;          // 32 x k-pairs
constexpr int kHKP = kU / 2;          // 64 h k-pairs
constexpr int kKP  = kXKP + kHKP;     // 96
constexpr int kCols = 256;

constexpr int kWsmF    = kKP * kCols * 2;          // 49152 floats (192 KB)
constexpr int kVxOff   = kWsmF;                    // x: [32 xkp][8 row][2 par]
constexpr int kHbOff   = kVxOff + kXKP * 16;       // h: 2 buffers x 1024 f
constexpr int kPbufOff = kHbOff + 2 * kHKP * 16;   // 3 slots x 2048 f (24 KB)
constexpr int kSmemBytes = (kPbufOff + 3 * 2048) * 4;   // 231424 B
}  // namespace

typedef unsigned long long ull;

__device__ __forceinline__ ull pk2(float a, float b) {
    ull r;
    asm("mov.b64 %0, {%1, %2};" : "=l"(r) : "f"(a), "f"(b));
    return r;
}
__device__ __forceinline__ void upk2(ull v, float& a, float& b) {
    asm("mov.b64 {%0, %1}, %2;" : "=f"(a), "=f"(b) : "l"(v));
}
__device__ __forceinline__ void fma2(ull& d, ull a, ull b) {
    asm("fma.rn.f32x2 %0, %1, %2, %0;" : "+l"(d) : "l"(a), "l"(b));
}
__device__ __forceinline__ void add2(ull& d, ull a) {
    asm("add.rn.f32x2 %0, %0, %1;" : "+l"(d) : "l"(a));
}
__device__ __forceinline__ float rcpa(float x) {
    float r;
    asm("rcp.approx.f32 %0, %1;" : "=f"(r) : "f"(x));
    return r;
}
__device__ __forceinline__ float sigf(float x) {
    return rcpa(1.0f + __expf(-x));
}
__device__ __forceinline__ float tanh_acc(float x) {
    float e = __expf(-2.0f * fabsf(x));
    float r = (1.0f - e) * rcpa(1.0f + e);
    return copysignf(r, x);
}
__device__ __forceinline__ uint32_t smem_u32(const void* p) {
    uint32_t a;
    asm("{ .reg .u64 t; cvta.to.shared.u64 t, %1; cvt.u32.u64 %0, t; }"
        : "=r"(a) : "l"(p));
    return a;
}

// GEMV over k-pairs [kp0, kp1): weights at GLOBAL kp = kp + wofs, values LOCAL
__device__ __forceinline__ void gemv_part(const ulonglong2* __restrict__ w2,
                                          const ulonglong2* __restrict__ v2,
                                          int wofs, int kp0, int kp1, int tidw,
                                          ull a0[8], ull a1[8]) {
#pragma unroll 8
    for (int kp = kp0; kp < kp1; ++kp) {
        ulonglong2 w = w2[(kp + wofs) * 128 + tidw];  // .x=(ke,ko)@j0 .y=@j1
        ulonglong2 vA = v2[kp * 4 + 0];               // rows 0,1
        ulonglong2 vB = v2[kp * 4 + 1];               // rows 2,3
        ulonglong2 vC = v2[kp * 4 + 2];               // rows 4,5
        ulonglong2 vD = v2[kp * 4 + 3];               // rows 6,7
        fma2(a0[0], vA.x, w.x); fma2(a0[1], vA.y, w.x);
        fma2(a0[2], vB.x, w.x); fma2(a0[3], vB.y, w.x);
        fma2(a0[4], vC.x, w.x); fma2(a0[5], vC.y, w.x);
        fma2(a0[6], vD.x, w.x); fma2(a0[7], vD.y, w.x);
        fma2(a1[0], vA.x, w.y); fma2(a1[1], vA.y, w.y);
        fma2(a1[2], vB.x, w.y); fma2(a1[3], vB.y, w.y);
        fma2(a1[4], vC.x, w.y); fma2(a1[5], vC.y, w.y);
        fma2(a1[6], vD.x, w.y); fma2(a1[7], vD.y, w.y);
    }
}

__global__ void __cluster_dims__(2, 1, 1) __launch_bounds__(kThreads, 1)
lstm_fused_kernel(const float* __restrict__ x,
                  const float* __restrict__ Wf, const float* __restrict__ Uf, const float* __restrict__ bf,
                  const float* __restrict__ Wi, const float* __restrict__ Ui, const float* __restrict__ bi,
                  const float* __restrict__ Wc, const float* __restrict__ Uc, const float* __restrict__ bc,
                  const float* __restrict__ Wo, const float* __restrict__ Uo, const float* __restrict__ bo,
                  float* __restrict__ out) {
    extern __shared__ float smem[];
    float* wsm   = smem;                       // [kp][j][par]
    float* vx    = smem + kVxOff;              // [xkp][row][par]   (single)
    float* hb0   = smem + kHbOff;              // [hkp][row][par]   (double)
    float* hb1   = hb0 + kHKP * 16;
    float* pbufF = smem + kPbufOff;            // 3 partial slots; slot0=gbuf
    ull*   pb2   = (ull*)pbufF;

    const int tid = threadIdx.x;
    uint32_t rank;
    asm("mov.u32 %0, %%cluster_ctarank;" : "=r"(rank));
    const int cl = blockIdx.x >> 1;

    const int q    = tid >> 7;                 // 0..3
    const int tidw = tid & 127;

    // x mapping (q1 does prefetch/stash): thread -> (row, 4-float d-group)
    const int xrow = tidw & 7;
    const int xdg  = tidw >> 3;
    const float4* xbase =
        (const float4*)(x + ((size_t)(cl * kR + xrow) * kT) * kD) + xdg;

    // q1 preloads x_0, x_1 up front (overlaps weight staging)
    float4 x0 = make_float4(0, 0, 0, 0), x1 = make_float4(0, 0, 0, 0);
    if (q == 1) {
        x0 = __ldg(xbase);
        x1 = __ldg(xbase + 16);                // +kD/4 float4 = one timestep
    }

    // ---- stage fused weight block ------------------------------------------
    for (int idx = tid; idx < 192 * kCols; idx += kThreads) {
        int k = idx >> 8;
        int j = idx & 255;
        int g = j >> 6;
        int u = (int)rank * 64 + (j & 63);
        float w;
        if (k < kD) {
            const float* src = (g == 0) ? Wf : (g == 1) ? Wi : (g == 2) ? Wc : Wo;
            w = src[k * kU + u];
        } else {
            const float* src = (g == 0) ? Uf : (g == 1) ? Ui : (g == 2) ? Uc : Uo;
            w = src[(k - kD) * kU + u];
        }
        wsm[(k >> 1) * 512 + j * 2 + (k & 1)] = w;
    }

    // ---- per-thread column / bias (q0 applies bias in combine) -------------
    const int j0 = 2 * tidw;
    const int g0 = j0 >> 6;
    const int u0 = (int)rank * 64 + (j0 & 63);
    const float* bsrc = (g0 == 0) ? bf : (g0 == 1) ? bi : (g0 == 2) ? bc : bo;
    const ull biasp = pk2(bsrc[u0], bsrc[u0 + 1]);

    // gate-math mapping (q0 only): u' = tid&63, rows rowbase..rowbase+3
    const int gup  = tid & 63;
    const int gu   = (int)rank * 64 + gup;
    const int rowbase = (tid >> 6) * 4;        // 0 or 4 (valid for tid<128)

    // peer CTA's hb0 shared-address (cluster DSMEM)
    uint32_t peer_hb0;
    {
        uint32_t prank = rank ^ 1u;
        uint32_t my_hb0 = smem_u32(hb0);
        asm("mapa.shared::cluster.u32 %0, %1, %2;"
            : "=r"(peer_hb0) : "r"(my_hb0), "r"(prank));
    }

    // ---- init: h_0 = 0 (own buffer), stash x_0 ------------------------------
    for (int i = tid; i < kHKP * 16; i += kThreads) hb0[i] = 0.0f;
    if (q == 1) {
        *(float2*)&vx[(2 * xdg + 0) * 16 + xrow * 2] = make_float2(x0.x, x0.y);
        *(float2*)&vx[(2 * xdg + 1) * 16 + xrow * 2] = make_float2(x0.z, x0.w);
    }
    __syncthreads();

    const ulonglong2* w2  = (const ulonglong2*)wsm;
    const ulonglong2* vx2 = (const ulonglong2*)vx;

    // accumulators carry x(t) contribution into iteration t
    ull a0[8], a1[8];
#pragma unroll
    for (int r = 0; r < 8; ++r) { a0[r] = 0ull; a1[r] = 0ull; }
    float creg[4] = {0.0f, 0.0f, 0.0f, 0.0f};

    // init x-GEMV for step 0 (q1-3: x kp split 11/11/10), then stash x_1
    if (q >= 1) {
        int qi = q - 1;
        int k0 = qi * 11, k1 = (qi == 2) ? kXKP : k0 + 11;
        gemv_part(w2, vx2, 0, k0, k1, tidw, a0, a1);
        asm volatile("bar.sync 2, 384;" ::: "memory");
        if (q == 1) {
            *(float2*)&vx[(2 * xdg + 0) * 16 + xrow * 2] = make_float2(x1.x, x1.y);
            *(float2*)&vx[(2 * xdg + 1) * 16 + xrow * 2] = make_float2(x1.z, x1.w);
        }
    }
    __syncthreads();
    // cluster entry sync (also orders nothing remote yet; cheap, once)
    asm volatile("barrier.cluster.arrive.aligned;" ::: "memory");
    asm volatile("barrier.cluster.wait.aligned;"   ::: "memory");

    int cur = 0;
    for (int t = 0; t < kT; ++t) {
        // q1: prefetch x_{t+2} (DRAM hidden behind h-GEMV)
        float4 xn = make_float4(0, 0, 0, 0);
        if (q == 1 && t + 2 < kT) xn = __ldg(xbase + (size_t)(t + 2) * 16);

        // ---- h-part GEMV (adds onto carried x(t) partials) -----------------
        const ulonglong2* hq2 = (const ulonglong2*)(cur ? hb1 : hb0);
        gemv_part(w2, hq2, kXKP, q * 16, q * 16 + 16, tidw, a0, a1);

        // lane-sum -> gfp[r] = (sum_j0, sum_j1); reset accs for next x-GEMV
        ull gfp[8];
#pragma unroll
        for (int r = 0; r < 8; ++r) {
            float s0lo, s0hi, s1lo, s1hi;
            upk2(a0[r], s0lo, s0hi);
            upk2(a1[r], s1lo, s1hi);
            gfp[r] = pk2(s0lo + s0hi, s1lo + s1hi);
            a0[r] = 0ull; a1[r] = 0ull;
        }
        if (q != 0) {
#pragma unroll
            for (int r = 0; r < 8; ++r)
                pb2[((q - 1) * 1024) + r * 128 + tidw] = gfp[r];
        }
        __syncthreads();                        // pbuf ready; h/x reads done

        if (tid < 128) {
            // ---- q0: combine + gate math + h stores ------------------------
#pragma unroll
            for (int r = 0; r < 8; ++r) {
                add2(gfp[r], pb2[0 * 1024 + r * 128 + tidw]);
                add2(gfp[r], pb2[1 * 1024 + r * 128 + tidw]);
                add2(gfp[r], pb2[2 * 1024 + r * 128 + tidw]);
                add2(gfp[r], biasp);
            }
            // gbuf write aliases pbuf slot0: same ull slot this thread read
#pragma unroll
            for (int r = 0; r < 8; ++r)
                pb2[r * 128 + tidw] = gfp[r];
            asm volatile("bar.sync 1, 128;" ::: "memory");

            float hv[4];
#pragma unroll
            for (int rr = 0; rr < 4; ++rr) {
                int row = rowbase + rr;
                const float* gb = pbufF + row * kCols + gup;
                float f  = sigf(gb[0]);
                float ii = sigf(gb[64]);
                float cd = tanh_acc(gb[128]);
                float o  = sigf(gb[192]);
                float c  = f * creg[rr] + ii * cd;
                creg[rr] = c;
                hv[rr] = o * tanh_acc(c);
            }
            if (t < kT - 1) {
                float* hbn = cur ? hb0 : hb1;   // write NEXT buffer
                uint32_t pbase = peer_hb0 + (cur ? 0u : 4096u);
#pragma unroll
                for (int rr = 0; rr < 4; ++rr) {
                    int row = rowbase + rr;
                    int off = (gu >> 1) * 16 + row * 2 + (gu & 1);
                    hbn[off] = hv[rr];                              // own copy
                    asm volatile("st.shared::cluster.b32 [%0], %1;" // peer copy
                                 :: "r"(pbase + (uint32_t)(off * 4)),
                                    "r"(__float_as_uint(hv[rr])) : "memory");
                }
            } else {
#pragma unroll
                for (int rr = 0; rr < 4; ++rr)
                    out[(size_t)(cl * kR + rowbase + rr) * kU + gu] = hv[rr];
            }
        } else {
            // ---- q1-3: x-GEMV for step t+1 (reads vx = x_{t+1}) ------------
            if (t + 1 < kT) {
                int qi = q - 1;
                int k0 = qi * 11, k1 = (qi == 2) ? kXKP : k0 + 11;
                gemv_part(w2, vx2, 0, k0, k1, tidw, a0, a1);
            }
            asm volatile("bar.sync 2, 384;" ::: "memory");
            if (q == 1 && t + 2 < kT) {         // stash x_{t+2} (reads done)
                *(float2*)&vx[(2 * xdg + 0) * 16 + xrow * 2] = make_float2(xn.x, xn.y);
                *(float2*)&vx[(2 * xdg + 1) * 16 + xrow * 2] = make_float2(xn.z, xn.w);
            }
        }

        // cluster barrier: rejoins the CTA (all 512 threads) AND releases the
        // DSMEM h stores to the peer (acq_rel) — one sync, two jobs.
        asm volatile("barrier.cluster.arrive.aligned;" ::: "memory");
        asm volatile("barrier.cluster.wait.aligned;"   ::: "memory");
        cur ^= 1;
    }
}

extern "C" void kernel_launch(void* const* d_in, const int* in_sizes, int n_in,
                              void* d_out, int out_size) {
    (void)in_sizes; (void)n_in; (void)out_size;
    const float* x  = (const float*)d_in[0];
    const float* Wf = (const float*)d_in[1];
    const float* Uf = (const float*)d_in[2];
    const float* bf = (const float*)d_in[3];
    const float* Wi = (const float*)d_in[4];
    const float* Ui = (const float*)d_in[5];
    const float* bi = (const float*)d_in[6];
    const float* Wc = (const float*)d_in[7];
    const float* Uc = (const float*)d_in[8];
    const float* bc = (const float*)d_in[9];
    const float* Wo = (const float*)d_in[10];
    const float* Uo = (const float*)d_in[11];
    const float* bo = (const float*)d_in[12];
    float* out = (float*)d_out;

    cudaFuncSetAttribute(lstm_fused_kernel,
                         cudaFuncAttributeMaxDynamicSharedMemorySize, kSmemBytes);
    const int grid = 64 * 2;   // 64 clusters x 2 CTAs
    lstm_fused_kernel<<<grid, kThreads, kSmemBytes>>>(
        x, Wf, Uf, bf, Wi, Ui, bi, Wc, Uc, bc, Wo, Uo, bo, out);
}

// round 12
// speedup vs baseline: 1.4257x; 1.0985x over previous
#include <cuda_runtime.h>
#include <cstdint>

// ---------------------------------------------------------------------------
// Fused LSTM, persistent-cluster design for GB300 (sm_103a).   Round 11.
//
//   B=512, T=1024, D=64, U=128.  out = h_T  [512,128] fp32.
//
// 64 clusters x 2 CTAs, 256 threads/CTA (2 warps/SMSP, ~200 regs/thread).
// CTA rank r owns u-cols [64r,64r+64) of all 4 gates (256 output cols).
// KEY CHANGE vs R10: the h-part (recurrent) weights live in REGISTERS.
//   2-way K split: group g2 = tid>>7 owns h-kp [32*g2, 32*g2+32) and
//   x-kp [16*g2, 16*g2+16). Per thread: 32 h-kp x 2 cols x 2 par =
//   128 weight floats held in wh0[32]/wh1[32] (ull pairs) permanently.
//   x-weights (64 KB) stay in SMEM. This removes ~2/3 of the per-step
//   weight smem traffic that bound R8/R10 (L1=65%).
// Lockstep step (R8-proven sync): GEMV (h from regs + x from smem)
//   -> lane-sum -> group1 publishes pbuf -> sync -> group0 combine+bias
//   -> gbuf (group1 stashes x_{t+1}) -> sync -> gate math (2 rows/thread)
//   -> h stores (own + peer DSMEM) -> barrier.cluster (release + lockstep).
// ---------------------------------------------------------------------------

namespace {
constexpr int kT = 1024;
constexpr int kD = 64;
constexpr int kU = 128;
constexpr int kR = 8;                 // batch rows per cluster
constexpr int kThreads = 256;
constexpr int kXKP = kD / 2;          // 32 x k-pairs
constexpr int kHKP = kU / 2;          // 64 h k-pairs
constexpr int kCols = 256;

// smem floats
constexpr int kXwF   = kXKP * kCols * 2;          // 16384 (64 KB) x-weights
constexpr int kVxOff = kXwF;                      // x values: 512 f
constexpr int kHbOff = kVxOff + kXKP * 16;        // h: 2 buffers x 1024 f
constexpr int kPbOff = kHbOff + 2 * kHKP * 16;    // pbuf: 2048 f (1024 ull)
constexpr int kGbOff = kPbOff + 2048;             // gbuf: 2048 f
constexpr int kHwOff = kGbOff + 2048;             // TEMP h-weights: 32768 f
constexpr int kSmemBytes = (kHwOff + kHKP * kCols * 2) * 4;   // 223232 B
}  // namespace

typedef unsigned long long ull;

__device__ __forceinline__ ull pk2(float a, float b) {
    ull r;
    asm("mov.b64 %0, {%1, %2};" : "=l"(r) : "f"(a), "f"(b));
    return r;
}
__device__ __forceinline__ void upk2(ull v, float& a, float& b) {
    asm("mov.b64 {%0, %1}, %2;" : "=f"(a), "=f"(b) : "l"(v));
}
__device__ __forceinline__ void fma2(ull& d, ull a, ull b) {
    asm("fma.rn.f32x2 %0, %1, %2, %0;" : "+l"(d) : "l"(a), "l"(b));
}
__device__ __forceinline__ void add2(ull& d, ull a) {
    asm("add.rn.f32x2 %0, %0, %1;" : "+l"(d) : "l"(a));
}
__device__ __forceinline__ float rcpa(float x) {
    float r;
    asm("rcp.approx.f32 %0, %1;" : "=f"(r) : "f"(x));
    return r;
}
__device__ __forceinline__ float sigf(float x) {
    return rcpa(1.0f + __expf(-x));
}
__device__ __forceinline__ float tanh_acc(float x) {
    float e = __expf(-2.0f * fabsf(x));
    float r = (1.0f - e) * rcpa(1.0f + e);
    return copysignf(r, x);
}
__device__ __forceinline__ uint32_t smem_u32(const void* p) {
    uint32_t a;
    asm("{ .reg .u64 t; cvta.to.shared.u64 t, %1; cvt.u32.u64 %0, t; }"
        : "=r"(a) : "l"(p));
    return a;
}

__global__ void __cluster_dims__(2, 1, 1) __launch_bounds__(kThreads, 1)
lstm_fused_kernel(const float* __restrict__ x,
                  const float* __restrict__ Wf, const float* __restrict__ Uf, const float* __restrict__ bf,
                  const float* __restrict__ Wi, const float* __restrict__ Ui, const float* __restrict__ bi,
                  const float* __restrict__ Wc, const float* __restrict__ Uc, const float* __restrict__ bc,
                  const float* __restrict__ Wo, const float* __restrict__ Uo, const float* __restrict__ bo,
                  float* __restrict__ out) {
    extern __shared__ float smem[];
    float* xw    = smem;                       // [xkp][j][par]  (persistent)
    float* vx    = smem + kVxOff;              // [xkp][row][par] (single buf)
    float* hb0   = smem + kHbOff;              // [hkp][row][par] (double buf)
    float* hb1   = hb0 + kHKP * 16;
    ull*   pb2   = (ull*)(smem + kPbOff);      // pbuf: [r][tidw] ull
    float* gbuf  = smem + kGbOff;              // [row][256]
    float* hwt   = smem + kHwOff;              // TEMP staged h-weights

    const int tid = threadIdx.x;
    uint32_t rank;
    asm("mov.u32 %0, %%cluster_ctarank;" : "=r"(rank));
    const int cl = blockIdx.x >> 1;

    const int g2   = tid >> 7;                 // K-group 0/1
    const int tidw = tid & 127;                // column-thread id in group

    // x prefetch/stash mapping (group1): thread -> (row, 4-float d-group)
    const int xrow = tidw & 7;
    const int xdg  = tidw >> 3;                // 0..15
    const float4* xbase =
        (const float4*)(x + ((size_t)(cl * kR + xrow) * kT) * kD) + xdg;

    // ---- stage weights: x -> persistent xw, h -> temp hwt -------------------
    for (int idx = tid; idx < 192 * kCols; idx += kThreads) {
        int k = idx >> 8;                      // 0..191
        int j = idx & 255;
        int g = j >> 6;
        int u = (int)rank * 64 + (j & 63);
        if (k < kD) {
            const float* src = (g == 0) ? Wf : (g == 1) ? Wi : (g == 2) ? Wc : Wo;
            xw[(k >> 1) * 512 + j * 2 + (k & 1)] = src[k * kU + u];
        } else {
            int hk = k - kD;                   // 0..127
            const float* src = (g == 0) ? Uf : (g == 1) ? Ui : (g == 2) ? Uc : Uo;
            hwt[(hk >> 1) * 512 + j * 2 + (hk & 1)] = src[hk * kU + u];
        }
    }
    __syncthreads();

    // ---- copy this thread's h-weight slice into registers -------------------
    // wh0[i]/wh1[i] = (ke,ko) pair for cols j0/j0+1 at h-kp = g2*32+i
    ull wh0[32], wh1[32];
    {
        const ulonglong2* hw2 = (const ulonglong2*)hwt;
#pragma unroll
        for (int i = 0; i < 32; ++i) {
            ulonglong2 w = hw2[(g2 * 32 + i) * 128 + tidw];
            wh0[i] = w.x;
            wh1[i] = w.y;
        }
    }

    // ---- per-thread column / bias (group0 applies bias in combine) ----------
    const int j0 = 2 * tidw;
    const int g0 = j0 >> 6;
    const int u0 = (int)rank * 64 + (j0 & 63);
    const float* bsrc = (g0 == 0) ? bf : (g0 == 1) ? bi : (g0 == 2) ? bc : bo;
    const ull biasp = pk2(bsrc[u0], bsrc[u0 + 1]);

    // gate-math mapping: thread -> (u' = tid&63, rows grow0, grow0+1)
    const int gup   = tid & 63;
    const int gu    = (int)rank * 64 + gup;
    const int grow0 = (tid >> 6) * 2;          // 0,2,4,6

    // peer CTA's hb0 shared-address (cluster DSMEM)
    uint32_t peer_hb0;
    {
        uint32_t prank = rank ^ 1u;
        uint32_t my_hb0 = smem_u32(hb0);
        asm("mapa.shared::cluster.u32 %0, %1, %2;"
            : "=r"(peer_hb0) : "r"(my_hb0), "r"(prank));
    }

    // ---- init: h_0 = 0 (own buffer), stash x_0 ------------------------------
    for (int i = tid; i < kHKP * 16; i += kThreads) hb0[i] = 0.0f;
    if (g2 == 1) {
        float4 x0 = __ldg(xbase);
        *(float2*)&vx[(2 * xdg + 0) * 16 + xrow * 2] = make_float2(x0.x, x0.y);
        *(float2*)&vx[(2 * xdg + 1) * 16 + xrow * 2] = make_float2(x0.z, x0.w);
    }
    float creg[2] = {0.0f, 0.0f};
    __syncthreads();
    // cluster entry sync before any remote traffic
    asm volatile("barrier.cluster.arrive.aligned;" ::: "memory");
    asm volatile("barrier.cluster.wait.aligned;"   ::: "memory");

    const ulonglong2* xw2 = (const ulonglong2*)xw;
    const ulonglong2* vx2 = (const ulonglong2*)vx;

    int cur = 0;
    for (int t = 0; t < kT; ++t) {
        // group1: prefetch x_{t+1} (DRAM hidden behind GEMV)
        float4 xn = make_float4(0, 0, 0, 0);
        if (g2 == 1 && t + 1 < kT) xn = __ldg(xbase + (size_t)(t + 1) * 16);

        const ulonglong2* hv2 = (const ulonglong2*)(cur ? hb1 : hb0);

        ull a0[8], a1[8];
#pragma unroll
        for (int r = 0; r < 8; ++r) { a0[r] = 0ull; a1[r] = 0ull; }

        // ---- h-part GEMV: weights from REGISTERS ---------------------------
#pragma unroll
        for (int i = 0; i < 32; ++i) {
            int kp = g2 * 32 + i;
            ulonglong2 vA = hv2[kp * 4 + 0];   // rows 0,1
            ulonglong2 vB = hv2[kp * 4 + 1];   // rows 2,3
            ulonglong2 vC = hv2[kp * 4 + 2];   // rows 4,5
            ulonglong2 vD = hv2[kp * 4 + 3];   // rows 6,7
            fma2(a0[0], vA.x, wh0[i]); fma2(a0[1], vA.y, wh0[i]);
            fma2(a0[2], vB.x, wh0[i]); fma2(a0[3], vB.y, wh0[i]);
            fma2(a0[4], vC.x, wh0[i]); fma2(a0[5], vC.y, wh0[i]);
            fma2(a0[6], vD.x, wh0[i]); fma2(a0[7], vD.y, wh0[i]);
            fma2(a1[0], vA.x, wh1[i]); fma2(a1[1], vA.y, wh1[i]);
            fma2(a1[2], vB.x, wh1[i]); fma2(a1[3], vB.y, wh1[i]);
            fma2(a1[4], vC.x, wh1[i]); fma2(a1[5], vC.y, wh1[i]);
            fma2(a1[6], vD.x, wh1[i]); fma2(a1[7], vD.y, wh1[i]);
        }

        // ---- x-part GEMV: weights from SMEM --------------------------------
#pragma unroll 4
        for (int i = 0; i < 16; ++i) {
            int kp = g2 * 16 + i;
            ulonglong2 w = xw2[kp * 128 + tidw];
            ulonglong2 vA = vx2[kp * 4 + 0];
            ulonglong2 vB = vx2[kp * 4 + 1];
            ulonglong2 vC = vx2[kp * 4 + 2];
            ulonglong2 vD = vx2[kp * 4 + 3];
            fma2(a0[0], vA.x, w.x); fma2(a0[1], vA.y, w.x);
            fma2(a0[2], vB.x, w.x); fma2(a0[3], vB.y, w.x);
            fma2(a0[4], vC.x, w.x); fma2(a0[5], vC.y, w.x);
            fma2(a0[6], vD.x, w.x); fma2(a0[7], vD.y, w.x);
            fma2(a1[0], vA.x, w.y); fma2(a1[1], vA.y, w.y);
            fma2(a1[2], vB.x, w.y); fma2(a1[3], vB.y, w.y);
            fma2(a1[4], vC.x, w.y); fma2(a1[5], vC.y, w.y);
            fma2(a1[6], vD.x, w.y); fma2(a1[7], vD.y, w.y);
        }

        // lane-sum -> gfp[r] = (sum@j0, sum@j1)
        ull gfp[8];
#pragma unroll
        for (int r = 0; r < 8; ++r) {
            float s0lo, s0hi, s1lo, s1hi;
            upk2(a0[r], s0lo, s0hi);
            upk2(a1[r], s1lo, s1hi);
            gfp[r] = pk2(s0lo + s0hi, s1lo + s1hi);
        }
        if (g2 == 1) {
#pragma unroll
            for (int r = 0; r < 8; ++r)
                pb2[r * 128 + tidw] = gfp[r];
        }
        __syncthreads();                        // pbuf ready; h/x reads done

        if (g2 == 0) {
            // combine + bias, scatter to gbuf
#pragma unroll
            for (int r = 0; r < 8; ++r) {
                add2(gfp[r], pb2[r * 128 + tidw]);
                add2(gfp[r], biasp);
                *(ull*)&gbuf[r * kCols + j0] = gfp[r];
            }
        } else if (t + 1 < kT) {
            // stash x_{t+1} (all x reads completed at the sync above)
            *(float2*)&vx[(2 * xdg + 0) * 16 + xrow * 2] = make_float2(xn.x, xn.y);
            *(float2*)&vx[(2 * xdg + 1) * 16 + xrow * 2] = make_float2(xn.z, xn.w);
        }
        __syncthreads();                        // gbuf ready

        // ---- gate math: 2 (row,u') per thread ------------------------------
        float hv[2];
#pragma unroll
        for (int rr = 0; rr < 2; ++rr) {
            int row = grow0 + rr;
            const float* gb = gbuf + row * kCols + gup;
            float f  = sigf(gb[0]);
            float ii = sigf(gb[64]);
            float cd = tanh_acc(gb[128]);
            float o  = sigf(gb[192]);
            float c  = f * creg[rr] + ii * cd;
            creg[rr] = c;
            hv[rr] = o * tanh_acc(c);
        }
        if (t < kT - 1) {
            float* hbn = cur ? hb0 : hb1;       // write NEXT buffer
            uint32_t pbase = peer_hb0 + (cur ? 0u : 4096u);
#pragma unroll
            for (int rr = 0; rr < 2; ++rr) {
                int row = grow0 + rr;
                int off = (gu >> 1) * 16 + row * 2 + (gu & 1);
                hbn[off] = hv[rr];                              // own copy
                asm volatile("st.shared::cluster.b32 [%0], %1;" // peer copy
                             :: "r"(pbase + (uint32_t)(off * 4)),
                                "r"(__float_as_uint(hv[rr])) : "memory");
            }
        } else {
#pragma unroll
            for (int rr = 0; rr < 2; ++rr)
                out[(size_t)(cl * kR + grow0 + rr) * kU + gu] = hv[rr];
        }

        // cluster barrier: lockstep + release DSMEM h stores (R8-proven)
        asm volatile("barrier.cluster.arrive.aligned;" ::: "memory");
        asm volatile("barrier.cluster.wait.aligned;"   ::: "memory");
        cur ^= 1;
    }
}

extern "C" void kernel_launch(void* const* d_in, const int* in_sizes, int n_in,
                              void* d_out, int out_size) {
    (void)in_sizes; (void)n_in; (void)out_size;
    const float* x  = (const float*)d_in[0];
    const float* Wf = (const float*)d_in[1];
    const float* Uf = (const float*)d_in[2];
    const float* bf = (const float*)d_in[3];
    const float* Wi = (const float*)d_in[4];
    const float* Ui = (const float*)d_in[5];
    const float* bi = (const float*)d_in[6];
    const float* Wc = (const float*)d_in[7];
    const float* Uc = (const float*)d_in[8];
    const float* bc = (const float*)d_in[9];
    const float* Wo = (const float*)d_in[10];
    const float* Uo = (const float*)d_in[11];
    const float* bo = (const float*)d_in[12];
    float* out = (float*)d_out;

    cudaFuncSetAttribute(lstm_fused_kernel,
                         cudaFuncAttributeMaxDynamicSharedMemorySize, kSmemBytes);
    const int grid = 64 * 2;   // 64 clusters x 2 CTAs
    lstm_fused_kernel<<<grid, kThreads, kSmemBytes>>>(
        x, Wf, Uf, bf, Wi, Ui, bi, Wc, Uc, bc, Wo, Uo, bo, out);
}

// round 13
// speedup vs baseline: 1.5076x; 1.0574x over previous
#include <cuda_runtime.h>
#include <cstdint>

// ---------------------------------------------------------------------------
// Fused LSTM, persistent-cluster design for GB300 (sm_103a).   Round 12.
//
//   B=512, T=1024, D=64, U=128.  out = h_T  [512,128] fp32.
//
// 64 clusters x 2 CTAs, 384 threads/CTA (3 warps/SMSP, ~160 regs/thread).
// CTA rank r owns u-cols [64r,64r+64) of all 4 gates (256 output cols).
// vs R11: 3-way K split so each SMSP has 3 warps (issue-latency hiding was
// the R11 bottleneck: issue=36.6%, occ=12.5%, fma only 38.7%).
//   group g3 = tid/128: h-kp 22/21/21, x-kp 10/11/11 (512 FFMA2 each).
//   h-weights live in REGISTERS (22 kp x 2 cols x 2 par = 88 regs max).
//   x-weights (64 KB) stay in SMEM. One-time h-weight staging buffer is
//   ALIASED over pbuf+gbuf (only used before the loop) -> 206,848 B smem.
// Lockstep step (R8/R11-proven): GEMV (h regs + x smem) -> lane-sum ->
//   g1/g2 publish pbuf -> sync -> g0 combine+bias -> gbuf (g1 stashes
//   x_{t+1}) -> sync -> gate math (threads 0-255, 2 rows each) -> h stores
//   (own + peer DSMEM) -> barrier.cluster (release + lockstep).
// ---------------------------------------------------------------------------

namespace {
constexpr int kT = 1024;
constexpr int kD = 64;
constexpr int kU = 128;
constexpr int kR = 8;                 // batch rows per cluster
constexpr int kThreads = 384;
constexpr int kXKP = kD / 2;          // 32 x k-pairs
constexpr int kHKP = kU / 2;          // 64 h k-pairs
constexpr int kCols = 256;

// smem floats
constexpr int kXwF   = kXKP * kCols * 2;          // 16384 (64 KB) x-weights
constexpr int kVxOff = kXwF;                      // x values: 512 f
constexpr int kHbOff = kVxOff + kXKP * 16;        // h: 2 buffers x 1024 f
constexpr int kPbOff = kHbOff + 2 * kHKP * 16;    // pbuf: 2 slots x 2048 f
constexpr int kGbOff = kPbOff + 2 * 2048;         // gbuf: 2048 f
constexpr int kHwOff = kPbOff;                    // TEMP h-weights ALIASED
constexpr int kHwF   = kHKP * kCols * 2;          // 32768 f
constexpr int kSmemBytes = (kHwOff + kHwF) * 4;   // 206848 B
static_assert(kGbOff + 2048 <= kHwOff + kHwF, "alias covers pbuf+gbuf");
}  // namespace

typedef unsigned long long ull;

__device__ __forceinline__ ull pk2(float a, float b) {
    ull r;
    asm("mov.b64 %0, {%1, %2};" : "=l"(r) : "f"(a), "f"(b));
    return r;
}
__device__ __forceinline__ void upk2(ull v, float& a, float& b) {
    asm("mov.b64 {%0, %1}, %2;" : "=f"(a), "=f"(b) : "l"(v));
}
__device__ __forceinline__ void fma2(ull& d, ull a, ull b) {
    asm("fma.rn.f32x2 %0, %1, %2, %0;" : "+l"(d) : "l"(a), "l"(b));
}
__device__ __forceinline__ void add2(ull& d, ull a) {
    asm("add.rn.f32x2 %0, %0, %1;" : "+l"(d) : "l"(a));
}
__device__ __forceinline__ float rcpa(float x) {
    float r;
    asm("rcp.approx.f32 %0, %1;" : "=f"(r) : "f"(x));
    return r;
}
__device__ __forceinline__ float sigf(float x) {
    return rcpa(1.0f + __expf(-x));
}
__device__ __forceinline__ float tanh_acc(float x) {
    float e = __expf(-2.0f * fabsf(x));
    float r = (1.0f - e) * rcpa(1.0f + e);
    return copysignf(r, x);
}
__device__ __forceinline__ uint32_t smem_u32(const void* p) {
    uint32_t a;
    asm("{ .reg .u64 t; cvta.to.shared.u64 t, %1; cvt.u32.u64 %0, t; }"
        : "=r"(a) : "l"(p));
    return a;
}

// h-GEMV: weights from registers (fully unrolled, compile-time trip count)
template <int HN>
__device__ __forceinline__ void gemv_h(const ulonglong2* __restrict__ hv2,
                                       int hk0, const ull* wh0, const ull* wh1,
                                       ull a0[8], ull a1[8]) {
#pragma unroll
    for (int i = 0; i < HN; ++i) {
        const ulonglong2* vp = hv2 + (hk0 + i) * 4;
        ulonglong2 vA = vp[0];     // rows 0,1
        ulonglong2 vB = vp[1];     // rows 2,3
        ulonglong2 vC = vp[2];     // rows 4,5
        ulonglong2 vD = vp[3];     // rows 6,7
        fma2(a0[0], vA.x, wh0[i]); fma2(a0[1], vA.y, wh0[i]);
        fma2(a0[2], vB.x, wh0[i]); fma2(a0[3], vB.y, wh0[i]);
        fma2(a0[4], vC.x, wh0[i]); fma2(a0[5], vC.y, wh0[i]);
        fma2(a0[6], vD.x, wh0[i]); fma2(a0[7], vD.y, wh0[i]);
        fma2(a1[0], vA.x, wh1[i]); fma2(a1[1], vA.y, wh1[i]);
        fma2(a1[2], vB.x, wh1[i]); fma2(a1[3], vB.y, wh1[i]);
        fma2(a1[4], vC.x, wh1[i]); fma2(a1[5], vC.y, wh1[i]);
        fma2(a1[6], vD.x, wh1[i]); fma2(a1[7], vD.y, wh1[i]);
    }
}

// x-GEMV: weights from SMEM
template <int XN>
__device__ __forceinline__ void gemv_x(const ulonglong2* __restrict__ xw2,
                                       const ulonglong2* __restrict__ vx2,
                                       int xk0, int tidw,
                                       ull a0[8], ull a1[8]) {
#pragma unroll
    for (int i = 0; i < XN; ++i) {
        int kp = xk0 + i;
        ulonglong2 w = xw2[kp * 128 + tidw];
        const ulonglong2* vp = vx2 + kp * 4;
        ulonglong2 vA = vp[0];
        ulonglong2 vB = vp[1];
        ulonglong2 vC = vp[2];
        ulonglong2 vD = vp[3];
        fma2(a0[0], vA.x, w.x); fma2(a0[1], vA.y, w.x);
        fma2(a0[2], vB.x, w.x); fma2(a0[3], vB.y, w.x);
        fma2(a0[4], vC.x, w.x); fma2(a0[5], vC.y, w.x);
        fma2(a0[6], vD.x, w.x); fma2(a0[7], vD.y, w.x);
        fma2(a1[0], vA.x, w.y); fma2(a1[1], vA.y, w.y);
        fma2(a1[2], vB.x, w.y); fma2(a1[3], vB.y, w.y);
        fma2(a1[4], vC.x, w.y); fma2(a1[5], vC.y, w.y);
        fma2(a1[6], vD.x, w.y); fma2(a1[7], vD.y, w.y);
    }
}

__global__ void __cluster_dims__(2, 1, 1) __launch_bounds__(kThreads, 1)
lstm_fused_kernel(const float* __restrict__ x,
                  const float* __restrict__ Wf, const float* __restrict__ Uf, const float* __restrict__ bf,
                  const float* __restrict__ Wi, const float* __restrict__ Ui, const float* __restrict__ bi,
                  const float* __restrict__ Wc, const float* __restrict__ Uc, const float* __restrict__ bc,
                  const float* __restrict__ Wo, const float* __restrict__ Uo, const float* __restrict__ bo,
                  float* __restrict__ out) {
    extern __shared__ float smem[];
    float* xw   = smem;                        // [xkp][j][par]  (persistent)
    float* vx   = smem + kVxOff;               // [xkp][row][par] (single buf)
    float* hb0  = smem + kHbOff;               // [hkp][row][par] (double buf)
    float* hb1  = hb0 + kHKP * 16;
    ull*   pb2  = (ull*)(smem + kPbOff);       // 2 slots x [r][tidw] ull
    float* gbuf = smem + kGbOff;               // [row][256]
    float* hwt  = smem + kHwOff;               // TEMP staged h-weights (alias)

    const int tid = threadIdx.x;
    uint32_t rank;
    asm("mov.u32 %0, %%cluster_ctarank;" : "=r"(rank));
    const int cl = blockIdx.x >> 1;

    const int g3   = tid >> 7;                 // K-group 0/1/2
    const int tidw = tid & 127;                // column-thread id in group

    // per-group kp ranges: h 22/21/21, x 10/11/11 (512 FFMA2 per thread each)
    const int hk0 = (g3 == 0) ? 0 : (1 + 21 * g3);     // 0, 22, 43
    const int hn  = (g3 == 0) ? 22 : 21;
    const int xk0 = (g3 == 0) ? 0 : (11 * g3 - 1);     // 0, 10, 21

    // x prefetch/stash mapping (group1): thread -> (row, 4-float d-group)
    const int xrow = tidw & 7;
    const int xdg  = tidw >> 3;                // 0..15
    const float4* xbase =
        (const float4*)(x + ((size_t)(cl * kR + xrow) * kT) * kD) + xdg;

    // ---- stage weights: x -> persistent xw, h -> temp hwt -------------------
    for (int idx = tid; idx < 192 * kCols; idx += kThreads) {
        int k = idx >> 8;                      // 0..191
        int j = idx & 255;
        int g = j >> 6;
        int u = (int)rank * 64 + (j & 63);
        if (k < kD) {
            const float* src = (g == 0) ? Wf : (g == 1) ? Wi : (g == 2) ? Wc : Wo;
            xw[(k >> 1) * 512 + j * 2 + (k & 1)] = src[k * kU + u];
        } else {
            int hk = k - kD;                   // 0..127
            const float* src = (g == 0) ? Uf : (g == 1) ? Ui : (g == 2) ? Uc : Uo;
            hwt[(hk >> 1) * 512 + j * 2 + (hk & 1)] = src[hk * kU + u];
        }
    }
    __syncthreads();

    // ---- copy this thread's h-weight slice into registers -------------------
    ull wh0[22], wh1[22];
    {
        const ulonglong2* hw2 = (const ulonglong2*)hwt;
        for (int i = 0; i < hn; ++i) {
            ulonglong2 w = hw2[(hk0 + i) * 128 + tidw];
            wh0[i] = w.x;
            wh1[i] = w.y;
        }
        if (hn < 22) { wh0[21] = 0ull; wh1[21] = 0ull; }
    }
    __syncthreads();                           // hwt dead; pbuf/gbuf live now

    // ---- per-thread column / bias (group0 applies bias in combine) ----------
    const int j0 = 2 * tidw;
    const int g0 = j0 >> 6;
    const int u0 = (int)rank * 64 + (j0 & 63);
    const float* bsrc = (g0 == 0) ? bf : (g0 == 1) ? bi : (g0 == 2) ? bc : bo;
    const ull biasp = pk2(bsrc[u0], bsrc[u0 + 1]);

    // gate-math mapping (threads 0-255): u' = tid&63, rows grow0, grow0+1
    const int gup   = tid & 63;
    const int gu    = (int)rank * 64 + gup;
    const int grow0 = ((tid >> 6) & 3) * 2;    // 0,2,4,6

    // peer CTA's hb0 shared-address (cluster DSMEM)
    uint32_t peer_hb0;
    {
        uint32_t prank = rank ^ 1u;
        uint32_t my_hb0 = smem_u32(hb0);
        asm("mapa.shared::cluster.u32 %0, %1, %2;"
            : "=r"(peer_hb0) : "r"(my_hb0), "r"(prank));
    }

    // ---- init: h_0 = 0 (own buffer), stash x_0 ------------------------------
    for (int i = tid; i < kHKP * 16; i += kThreads) hb0[i] = 0.0f;
    if (g3 == 1) {
        float4 x0 = __ldg(xbase);
        *(float2*)&vx[(2 * xdg + 0) * 16 + xrow * 2] = make_float2(x0.x, x0.y);
        *(float2*)&vx[(2 * xdg + 1) * 16 + xrow * 2] = make_float2(x0.z, x0.w);
    }
    float creg[2] = {0.0f, 0.0f};
    __syncthreads();
    // cluster entry sync before any remote traffic
    asm volatile("barrier.cluster.arrive.aligned;" ::: "memory");
    asm volatile("barrier.cluster.wait.aligned;"   ::: "memory");

    const ulonglong2* xw2 = (const ulonglong2*)xw;
    const ulonglong2* vx2 = (const ulonglong2*)vx;

    int cur = 0;
    for (int t = 0; t < kT; ++t) {
        // group1: prefetch x_{t+1} (DRAM hidden behind GEMV)
        float4 xn = make_float4(0, 0, 0, 0);
        if (g3 == 1 && t + 1 < kT) xn = __ldg(xbase + (size_t)(t + 1) * 16);

        const ulonglong2* hv2 = (const ulonglong2*)(cur ? hb1 : hb0);

        ull a0[8], a1[8];
#pragma unroll
        for (int r = 0; r < 8; ++r) { a0[r] = 0ull; a1[r] = 0ull; }

        // ---- GEMV: h from registers, x from smem ---------------------------
        if (g3 == 0) {
            gemv_h<22>(hv2, hk0, wh0, wh1, a0, a1);
            gemv_x<10>(xw2, vx2, xk0, tidw, a0, a1);
        } else {
            gemv_h<21>(hv2, hk0, wh0, wh1, a0, a1);
            gemv_x<11>(xw2, vx2, xk0, tidw, a0, a1);
        }

        // lane-sum -> gfp[r] = (sum@j0, sum@j1)
        ull gfp[8];
#pragma unroll
        for (int r = 0; r < 8; ++r) {
            float s0lo, s0hi, s1lo, s1hi;
            upk2(a0[r], s0lo, s0hi);
            upk2(a1[r], s1lo, s1hi);
            gfp[r] = pk2(s0lo + s0hi, s1lo + s1hi);
        }
        if (g3 != 0) {
#pragma unroll
            for (int r = 0; r < 8; ++r)
                pb2[(g3 - 1) * 1024 + r * 128 + tidw] = gfp[r];
        }
        __syncthreads();                        // pbuf ready; h/x reads done

        if (g3 == 0) {
            // combine + bias, scatter to gbuf
#pragma unroll
            for (int r = 0; r < 8; ++r) {
                add2(gfp[r], pb2[0 * 1024 + r * 128 + tidw]);
                add2(gfp[r], pb2[1 * 1024 + r * 128 + tidw]);
                add2(gfp[r], biasp);
                *(ull*)&gbuf[r * kCols + j0] = gfp[r];
            }
        } else if (g3 == 1 && t + 1 < kT) {
            // stash x_{t+1} (all x reads completed at the sync above)
            *(float2*)&vx[(2 * xdg + 0) * 16 + xrow * 2] = make_float2(xn.x, xn.y);
            *(float2*)&vx[(2 * xdg + 1) * 16 + xrow * 2] = make_float2(xn.z, xn.w);
        }
        __syncthreads();                        // gbuf ready

        // ---- gate math: threads 0-255, 2 (row,u') each ---------------------
        if (tid < 256) {
            float hv[2];
#pragma unroll
            for (int rr = 0; rr < 2; ++rr) {
                int row = grow0 + rr;
                const float* gb = gbuf + row * kCols + gup;
                float f  = sigf(gb[0]);
                float ii = sigf(gb[64]);
                float cd = tanh_acc(gb[128]);
                float o  = sigf(gb[192]);
                float c  = f * creg[rr] + ii * cd;
                creg[rr] = c;
                hv[rr] = o * tanh_acc(c);
            }
            if (t < kT - 1) {
                float* hbn = cur ? hb0 : hb1;   // write NEXT buffer
                uint32_t pbase = peer_hb0 + (cur ? 0u : 4096u);
#pragma unroll
                for (int rr = 0; rr < 2; ++rr) {
                    int row = grow0 + rr;
                    int off = (gu >> 1) * 16 + row * 2 + (gu & 1);
                    hbn[off] = hv[rr];                              // own copy
                    asm volatile("st.shared::cluster.b32 [%0], %1;" // peer copy
                                 :: "r"(pbase + (uint32_t)(off * 4)),
                                    "r"(__float_as_uint(hv[rr])) : "memory");
                }
            } else {
#pragma unroll
                for (int rr = 0; rr < 2; ++rr)
                    out[(size_t)(cl * kR + grow0 + rr) * kU + gu] = hv[rr];
            }
        }

        // cluster barrier: lockstep + release DSMEM h stores (proven)
        asm volatile("barrier.cluster.arrive.aligned;" ::: "memory");
        asm volatile("barrier.cluster.wait.aligned;"   ::: "memory");
        cur ^= 1;
    }
}

extern "C" void kernel_launch(void* const* d_in, const int* in_sizes, int n_in,
                              void* d_out, int out_size) {
    (void)in_sizes; (void)n_in; (void)out_size;
    const float* x  = (const float*)d_in[0];
    const float* Wf = (const float*)d_in[1];
    const float* Uf = (const float*)d_in[2];
    const float* bf = (const float*)d_in[3];
    const float* Wi = (const float*)d_in[4];
    const float* Ui = (const float*)d_in[5];
    const float* bi = (const float*)d_in[6];
    const float* Wc = (const float*)d_in[7];
    const float* Uc = (const float*)d_in[8];
    const float* bc = (const float*)d_in[9];
    const float* Wo = (const float*)d_in[10];
    const float* Uo = (const float*)d_in[11];
    const float* bo = (const float*)d_in[12];
    float* out = (float*)d_out;

    cudaFuncSetAttribute(lstm_fused_kernel,
                         cudaFuncAttributeMaxDynamicSharedMemorySize, kSmemBytes);
    const int grid = 64 * 2;   // 64 clusters x 2 CTAs
    lstm_fused_kernel<<<grid, kThreads, kSmemBytes>>>(
        x, Wf, Uf, bf, Wi, Ui, bi, Wc, Uc, bc, Wo, Uo, bo, out);
}